// round 14
// baseline (speedup 1.0000x reference)
#include <cuda_runtime.h>
#include <cuda_fp16.h>
#include <cstddef>
#include <cstdint>

#define N_NODES 100000
#define F_DIM   256
#define NNZ     1600000
#define NB1     98          // ceil(N_NODES/1024)

// ---------------- scratch (no allocation allowed) ----------------
// __device__ symbols are ONLY referenced from device code, never passed
// as kernel arguments from host.
__device__ __half g_xt[(size_t)N_NODES * F_DIM];  // GEMM output, fp16 (gathered)
__device__ __half g_m [(size_t)N_NODES * F_DIM];  // hyperedge accum, fp16 (gathered)
__device__ __half g_h [(size_t)N_NODES * F_DIM];  // layer-1 hidden, fp16

__device__ __half g_W1h[F_DIM * F_DIM];  // W1^T f16  [n][k]
__device__ __half g_W2h[F_DIM * F_DIM];  // W2^T f16  [n][k]

__device__ int g_degD[N_NODES];
__device__ int g_degB[N_NODES];
__device__ int g_offD[N_NODES];
__device__ int g_offB[N_NODES];
__device__ int g_curD[N_NODES];
__device__ int g_curB[N_NODES];
__device__ int g_adjD[NNZ];       // grouped by src: stores dst ids
__device__ int g_adjB[NNZ];       // grouped by dst: stores src ids
__device__ int g_bsumD[NB1];
__device__ int g_bsumB[NB1];

// ---------------- CSR build ----------------
__global__ void k_zero_counts() {
    int i = blockIdx.x * blockDim.x + threadIdx.x;
    if (i < N_NODES) { g_degD[i] = 0; g_degB[i] = 0; }
}

// 2 edges per thread via int2 loads on each half
__global__ void k_count(const int* __restrict__ ei) {
    int i = blockIdx.x * blockDim.x + threadIdx.x;
    if (i < NNZ / 2) {
        int2 s2 = ((const int2*)ei)[i];
        int2 d2 = ((const int2*)(ei + NNZ))[i];
        atomicAdd(&g_degD[s2.x], 1);
        atomicAdd(&g_degD[s2.y], 1);
        atomicAdd(&g_degB[d2.x], 1);
        atomicAdd(&g_degB[d2.y], 1);
    }
}

__global__ void k_scan1() {
    int which = blockIdx.y;
    const int* __restrict__ in  = which ? g_degB  : g_degD;
    int* __restrict__ out       = which ? g_offB  : g_offD;
    int* __restrict__ bsums     = which ? g_bsumB : g_bsumD;
    __shared__ int sh[1024];
    int g = blockIdx.x * 1024 + threadIdx.x;
    int v = (g < N_NODES) ? in[g] : 0;
    sh[threadIdx.x] = v;
    __syncthreads();
    #pragma unroll
    for (int off = 1; off < 1024; off <<= 1) {
        int t = (threadIdx.x >= off) ? sh[threadIdx.x - off] : 0;
        __syncthreads();
        sh[threadIdx.x] += t;
        __syncthreads();
    }
    if (g < N_NODES) out[g] = sh[threadIdx.x] - v;   // exclusive
    if (threadIdx.x == 1023) bsums[blockIdx.x] = sh[1023];
}

__global__ void k_scan2() {
    int* __restrict__ bsums = blockIdx.y ? g_bsumB : g_bsumD;
    __shared__ int sh[128];
    int v = (threadIdx.x < NB1) ? bsums[threadIdx.x] : 0;
    sh[threadIdx.x] = v;
    __syncthreads();
    #pragma unroll
    for (int off = 1; off < 128; off <<= 1) {
        int t = (threadIdx.x >= off) ? sh[threadIdx.x - off] : 0;
        __syncthreads();
        sh[threadIdx.x] += t;
        __syncthreads();
    }
    if (threadIdx.x < NB1) bsums[threadIdx.x] = sh[threadIdx.x] - v;
}

__global__ void k_scan3() {
    int which = blockIdx.y;
    int* __restrict__ out         = which ? g_offB  : g_offD;
    const int* __restrict__ bsums = which ? g_bsumB : g_bsumD;
    int* __restrict__ cur         = which ? g_curB  : g_curD;
    int g = blockIdx.x * 1024 + threadIdx.x;
    if (g < N_NODES) {
        int v = out[g] + bsums[blockIdx.x];
        out[g] = v;
        cur[g] = v;
    }
}

// fill only the dst-grouped CSR (needed by gather_n2e) — critical path.
// 2 edges per thread: two independent atomic chains in flight.
__global__ void k_fillB(const int* __restrict__ ei) {
    int i = blockIdx.x * blockDim.x + threadIdx.x;
    if (i < NNZ / 2) {
        int2 s2 = ((const int2*)ei)[i];
        int2 d2 = ((const int2*)(ei + NNZ))[i];
        g_adjB[atomicAdd(&g_curB[d2.x], 1)] = s2.x;
        g_adjB[atomicAdd(&g_curB[d2.y], 1)] = s2.y;
    }
}

// fill the src-grouped CSR (needed by gather_e2n) — overlapped off-path
__global__ void k_fillD(const int* __restrict__ ei) {
    int i = blockIdx.x * blockDim.x + threadIdx.x;
    if (i < NNZ / 2) {
        int2 s2 = ((const int2*)ei)[i];
        int2 d2 = ((const int2*)(ei + NNZ))[i];
        g_adjD[atomicAdd(&g_curD[s2.x], 1)] = d2.x;
        g_adjD[atomicAdd(&g_curD[s2.y], 1)] = d2.y;
    }
}

// ---------------- W prep: transpose + f16, both weights in one launch ----
// blockIdx.y: 0 -> W1, 1 -> W2
__global__ void k_prep_w(const float* __restrict__ W1,
                         const float* __restrict__ W2) {
    int which = blockIdx.y;
    const float* __restrict__ W = which ? W2 : W1;
    __half* dh = which ? g_W2h : g_W1h;
    int i = blockIdx.x * blockDim.x + threadIdx.x;   // 65536 per slice
    int k = i >> 8;
    int n = i & 255;
    dh[n * F_DIM + k] = __float2half_rn(W[k * F_DIM + n]);  // coalesced in n
}

// ---------------- HMMA GEMM via mma.sync (portable) ----------------
// g_xt[M,256](fp16) = A[M,256] @ W[256,256], single-pass f16, fp32 accum.
// CTA: 256 threads (8 warps as 4m x 2n), tile 128x128, K chunk 32.
#define KCH 32
#define LDA 40                        // padded row stride (halves)

__device__ __forceinline__ uint32_t smem_u32(const void* p) {
    uint32_t a;
    asm("{ .reg .u64 t; cvta.to.shared.u64 t, %1; cvt.u32.u64 %0, t; }"
        : "=r"(a) : "l"(p));
    return a;
}
__device__ __forceinline__ void ldsm4(uint32_t& r0, uint32_t& r1,
                                      uint32_t& r2, uint32_t& r3, uint32_t a) {
    asm volatile("ldmatrix.sync.aligned.m8n8.x4.shared.b16 {%0,%1,%2,%3}, [%4];"
                 : "=r"(r0), "=r"(r1), "=r"(r2), "=r"(r3) : "r"(a));
}
__device__ __forceinline__ void mma16816(float* d, const uint32_t* a,
                                         const uint32_t* b) {
    asm volatile(
        "mma.sync.aligned.m16n8k16.row.col.f32.f16.f16.f32 "
        "{%0,%1,%2,%3},{%4,%5,%6,%7},{%8,%9},{%0,%1,%2,%3};"
        : "+f"(d[0]), "+f"(d[1]), "+f"(d[2]), "+f"(d[3])
        : "r"(a[0]), "r"(a[1]), "r"(a[2]), "r"(a[3]), "r"(b[0]), "r"(b[1]));
}

__global__ __launch_bounds__(256, 2)
void k_gemm_mma(const float* __restrict__ A_ext, int use_h, int use_w2) {
    __shared__ __half As[128 * LDA];
    __shared__ __half Bs[128 * LDA];

    const __half* __restrict__ Wh = use_w2 ? g_W2h : g_W1h;

    int tid  = threadIdx.x;
    int wid  = tid >> 5;
    int lane = tid & 31;
    int wm   = wid & 3;        // warp m index (4) -> rows wm*32
    int wn   = wid >> 2;       // warp n index (2) -> cols wn*64
    int bm   = blockIdx.y * 128;
    int bn   = blockIdx.x * 128;

    uint32_t sA = smem_u32(As);
    uint32_t sB = smem_u32(Bs);

    float acc[2][8][4];
    #pragma unroll
    for (int i = 0; i < 2; ++i)
        #pragma unroll
        for (int j = 0; j < 8; ++j)
            #pragma unroll
            for (int c = 0; c < 4; ++c) acc[i][j][c] = 0.f;

    int lanerow = lane & 15;
    int lanek   = (lane >> 4) << 3;   // 0 or 8

    for (int k0 = 0; k0 < F_DIM; k0 += KCH) {
        // ---- A tile: 128 rows x 32 halves ----
        if (use_h) {
            #pragma unroll
            for (int l = 0; l < 2; ++l) {
                int idx = tid + l * 256;   // 0..511
                int m = idx >> 2;          // 0..127
                int j = idx & 3;           // uint4 -> klocal j*8
                int grow = bm + m;
                uint4 v = make_uint4(0u, 0u, 0u, 0u);
                if (grow < N_NODES)
                    v = *(const uint4*)(g_h + (size_t)grow * F_DIM + k0 + j * 8);
                *(uint4*)&As[m * LDA + j * 8] = v;
            }
        } else {
            #pragma unroll
            for (int l = 0; l < 4; ++l) {
                int idx = tid + l * 256;   // 0..1023
                int m = idx >> 3;          // 0..127
                int j = idx & 7;           // float4 -> klocal j*4
                int grow = bm + m;
                float4 v = make_float4(0.f, 0.f, 0.f, 0.f);
                if (grow < N_NODES)
                    v = *(const float4*)(A_ext + (size_t)grow * F_DIM + k0 + j * 4);
                int o = m * LDA + j * 4;
                *(__half2*)&As[o]     = __floats2half2_rn(v.x, v.y);
                *(__half2*)&As[o + 2] = __floats2half2_rn(v.z, v.w);
            }
        }
        // ---- B tile: 128 n-rows x 32 halves from Wh [n][k] ----
        {
            #pragma unroll
            for (int l = 0; l < 2; ++l) {
                int id2 = tid + l * 256;
                int n = id2 >> 2;          // 0..127
                int j = id2 & 3;           // uint4 -> klocal j*8
                *(uint4*)&Bs[n * LDA + j * 8] =
                    *(const uint4*)(Wh + (size_t)(bn + n) * F_DIM + k0 + j * 8);
            }
        }
        __syncthreads();

        #pragma unroll
        for (int ks = 0; ks < KCH; ks += 16) {
            uint32_t a[2][4];
            #pragma unroll
            for (int mf = 0; mf < 2; ++mf) {
                uint32_t off = (uint32_t)((wm * 32 + mf * 16 + lanerow) * LDA
                                          + ks + lanek) * 2;
                ldsm4(a[mf][0], a[mf][1], a[mf][2], a[mf][3], sA + off);
            }
            #pragma unroll
            for (int h = 0; h < 2; ++h) {      // two halves of 4 n-tiles
                uint32_t b[4][2];
                #pragma unroll
                for (int g = 0; g < 2; ++g) {  // each x4 covers 2 n-tiles
                    uint32_t off = (uint32_t)((wn * 64 + (h * 2 + g) * 16
                                               + lanerow) * LDA + ks + lanek) * 2;
                    uint32_t r0, r1, r2, r3;
                    ldsm4(r0, r1, r2, r3, sB + off);
                    b[g * 2][0] = r0; b[g * 2][1] = r2;
                    b[g * 2 + 1][0] = r1; b[g * 2 + 1][1] = r3;
                }
                #pragma unroll
                for (int mf = 0; mf < 2; ++mf)
                    #pragma unroll
                    for (int t = 0; t < 4; ++t)
                        mma16816(acc[mf][h * 4 + t], a[mf], b[t]);
            }
        }
        __syncthreads();
    }

    // ---- epilogue: write fp16 g_xt ----
    int qrow = lane >> 2;          // 0..7
    int qcol = (lane & 3) * 2;     // 0,2,4,6
    #pragma unroll
    for (int mf = 0; mf < 2; ++mf) {
        int r0 = bm + wm * 32 + mf * 16 + qrow;
        #pragma unroll
        for (int nt = 0; nt < 8; ++nt) {
            int col = bn + wn * 64 + nt * 8 + qcol;
            float* d = acc[mf][nt];
            if (r0 < N_NODES)
                *(__half2*)(g_xt + (size_t)r0 * F_DIM + col) =
                    __floats2half2_rn(d[0], d[1]);
            if (r0 + 8 < N_NODES)
                *(__half2*)(g_xt + (size_t)(r0 + 8) * F_DIM + col) =
                    __floats2half2_rn(d[2], d[3]);
        }
    }
}

// ---------------- fp16 row helpers ----------------
__device__ __forceinline__ void acc8_from_u4(float* acc, uint4 v) {
    __half2* h = (__half2*)&v;
    #pragma unroll
    for (int i = 0; i < 4; ++i) {
        float2 f = __half22float2(h[i]);
        acc[2 * i]     += f.x;
        acc[2 * i + 1] += f.y;
    }
}
__device__ __forceinline__ uint4 u4_from_8f(const float* s) {
    uint4 v;
    __half2* h = (__half2*)&v;
    #pragma unroll
    for (int i = 0; i < 4; ++i)
        h[i] = __floats2half2_rn(s[2 * i], s[2 * i + 1]);
    return v;
}

// ------- gather node -> hyperedge: g_m[e] = Binv[e] * sum_{src in e} g_xt[src]
__global__ __launch_bounds__(256)
void k_gather_n2e() {
    int w = (blockIdx.x * blockDim.x + threadIdx.x) >> 5;
    if (w >= N_NODES) return;
    int lane = threadIdx.x & 31;
    int off = g_offB[w];
    int deg = g_degB[w];
    const int* __restrict__ adj = g_adjB + off;

    float acc[8] = {0.f, 0.f, 0.f, 0.f, 0.f, 0.f, 0.f, 0.f};
    #pragma unroll 4
    for (int j = 0; j < deg; ++j) {
        int s = __ldg(adj + j);
        uint4 v = __ldg((const uint4*)(g_xt + (size_t)s * F_DIM) + lane);
        acc8_from_u4(acc, v);
    }
    float binv = deg > 0 ? 1.f / (float)deg : 0.f;
    #pragma unroll
    for (int i = 0; i < 8; ++i) acc[i] *= binv;
    *((uint4*)(g_m + (size_t)w * F_DIM) + lane) = u4_from_8f(acc);
}

__device__ __forceinline__ float prelu(float v, float a) {
    return v >= 0.f ? v : a * v;
}

// ------- gather hyperedge -> node, fused epilogue
// use_out: 1 -> write fp32 dout (+x residual), 0 -> write fp16 g_h
__global__ __launch_bounds__(256)
void k_gather_e2n(float* __restrict__ dout, const float* __restrict__ bias,
                  const float* __restrict__ aP, const float* __restrict__ xres,
                  int use_out, int addres) {
    int w = (blockIdx.x * blockDim.x + threadIdx.x) >> 5;
    if (w >= N_NODES) return;
    int lane = threadIdx.x & 31;
    int off = g_offD[w];
    int deg = g_degD[w];
    const int* __restrict__ adj = g_adjD + off;

    float acc[8] = {0.f, 0.f, 0.f, 0.f, 0.f, 0.f, 0.f, 0.f};
    #pragma unroll 4
    for (int j = 0; j < deg; ++j) {
        int e = __ldg(adj + j);
        uint4 v = __ldg((const uint4*)(g_m + (size_t)e * F_DIM) + lane);
        acc8_from_u4(acc, v);
    }
    float dinv = deg > 0 ? 1.f / (float)deg : 0.f;
    float av = __ldg(aP);
    float4 bb0 = *(const float4*)(bias + lane * 8);
    float4 bb1 = *(const float4*)(bias + lane * 8 + 4);
    float r[8];
    r[0] = fmaf(acc[0], dinv, bb0.x); r[1] = fmaf(acc[1], dinv, bb0.y);
    r[2] = fmaf(acc[2], dinv, bb0.z); r[3] = fmaf(acc[3], dinv, bb0.w);
    r[4] = fmaf(acc[4], dinv, bb1.x); r[5] = fmaf(acc[5], dinv, bb1.y);
    r[6] = fmaf(acc[6], dinv, bb1.z); r[7] = fmaf(acc[7], dinv, bb1.w);

    if (addres) {
        const float* xr = xres + (size_t)w * F_DIM + lane * 8;
        float4 x0 = __ldg((const float4*)xr);
        float4 x1 = __ldg((const float4*)(xr + 4));
        r[0] += x0.x; r[1] += x0.y; r[2] += x0.z; r[3] += x0.w;
        r[4] += x1.x; r[5] += x1.y; r[6] += x1.z; r[7] += x1.w;
    }
    #pragma unroll
    for (int i = 0; i < 8; ++i) r[i] = prelu(r[i], av);

    if (use_out) {
        float* dr = dout + (size_t)w * F_DIM + lane * 8;
        *(float4*)dr       = make_float4(r[0], r[1], r[2], r[3]);
        *(float4*)(dr + 4) = make_float4(r[4], r[5], r[6], r[7]);
    } else {
        *((uint4*)(g_h + (size_t)w * F_DIM) + lane) = u4_from_8f(r);
    }
}

// ---------------- launch ----------------
extern "C" void kernel_launch(void* const* d_in, const int* in_sizes, int n_in,
                              void* d_out, int out_size) {
    const float* x  = (const float*)d_in[0];
    const int*   ei = (const int*)  d_in[1];
    const float* W1 = (const float*)d_in[2];
    const float* b1 = (const float*)d_in[3];
    const float* W2 = (const float*)d_in[4];
    const float* b2 = (const float*)d_in[5];
    const float* a  = (const float*)d_in[6];
    float* out = (float*)d_out;

    // Host-side objects created once (no device memory involved). The launched
    // work is identical on every call.
    static cudaStream_t s_side = [] {
        cudaStream_t s = nullptr;
        cudaStreamCreateWithFlags(&s, cudaStreamNonBlocking);
        return s;
    }();
    static cudaStream_t s_fill = [] {
        cudaStream_t s = nullptr;
        cudaStreamCreateWithFlags(&s, cudaStreamNonBlocking);
        return s;
    }();
    static cudaEvent_t e_fork = [] {
        cudaEvent_t e = nullptr;
        cudaEventCreateWithFlags(&e, cudaEventDisableTiming);
        return e;
    }();
    static cudaEvent_t e_gemm1 = [] {
        cudaEvent_t e = nullptr;
        cudaEventCreateWithFlags(&e, cudaEventDisableTiming);
        return e;
    }();
    static cudaEvent_t e_scan = [] {
        cudaEvent_t e = nullptr;
        cudaEventCreateWithFlags(&e, cudaEventDisableTiming);
        return e;
    }();
    static cudaEvent_t e_fillD = [] {
        cudaEvent_t e = nullptr;
        cudaEventCreateWithFlags(&e, cudaEventDisableTiming);
        return e;
    }();

    const int GAT = (N_NODES * 32 + 255) / 256;   // warp per node
    dim3 ggrid(2, (N_NODES + 127) / 128);         // 2 n-tiles x 782 m-tiles

    // ---- fork: W prep + GEMM-1 on side stream ----
    cudaEventRecord(e_fork, 0);
    cudaStreamWaitEvent(s_side, e_fork, 0);
    k_prep_w<<<dim3(F_DIM * F_DIM / 256, 2), 256, 0, s_side>>>(W1, W2);
    k_gemm_mma<<<ggrid, 256, 0, s_side>>>(x, 0, 0);
    cudaEventRecord(e_gemm1, s_side);

    // ---- main stream: CSR build, B-side only on the critical path ----
    k_zero_counts<<<(N_NODES + 255) / 256, 256>>>();
    k_count<<<(NNZ / 2 + 255) / 256, 256>>>(ei);
    k_scan1<<<dim3(NB1, 2), 1024>>>();
    k_scan2<<<dim3(1, 2), 128>>>();
    k_scan3<<<dim3(NB1, 2), 1024>>>();
    cudaEventRecord(e_scan, 0);
    k_fillB<<<(NNZ / 2 + 255) / 256, 256>>>(ei);

    // ---- fill D-CSR off the critical path (overlaps gather_n2e) ----
    cudaStreamWaitEvent(s_fill, e_scan, 0);
    k_fillD<<<(NNZ / 2 + 255) / 256, 256, 0, s_fill>>>(ei);
    cudaEventRecord(e_fillD, s_fill);

    // join with GEMM-1, then layer-1 gathers
    cudaStreamWaitEvent(0, e_gemm1, 0);
    k_gather_n2e<<<GAT, 256>>>();
    cudaStreamWaitEvent(0, e_fillD, 0);
    k_gather_e2n<<<GAT, 256>>>(out, b1, a, x, 0, 0);

    // ---- layer 2 ----
    k_gemm_mma<<<ggrid, 256>>>(x /*unused*/, 1, 1);
    k_gather_n2e<<<GAT, 256>>>();
    k_gather_e2n<<<GAT, 256>>>(out, b2, a, x, 1, 1);
}

// round 15
// speedup vs baseline: 1.0281x; 1.0281x over previous
#include <cuda_runtime.h>
#include <cuda_fp16.h>
#include <cstddef>
#include <cstdint>

#define N_NODES 100000
#define F_DIM   256
#define NNZ     1600000
#define NB1     98          // ceil(N_NODES/1024)

// ---------------- scratch (no allocation allowed) ----------------
// __device__ symbols are ONLY referenced from device code, never passed
// as kernel arguments from host.
__device__ __half g_xt[(size_t)N_NODES * F_DIM];  // GEMM output, fp16 (gathered)
__device__ __half g_m [(size_t)N_NODES * F_DIM];  // hyperedge accum, fp16 (gathered)
__device__ __half g_h [(size_t)N_NODES * F_DIM];  // layer-1 hidden, fp16

__device__ __half g_W1h[F_DIM * F_DIM];  // W1^T f16  [n][k]
__device__ __half g_W2h[F_DIM * F_DIM];  // W2^T f16  [n][k]

__device__ int g_degD[N_NODES];
__device__ int g_degB[N_NODES];
__device__ int g_offD[N_NODES];   // BLOCK-LOCAL exclusive prefix
__device__ int g_offB[N_NODES];   // BLOCK-LOCAL exclusive prefix
__device__ int g_curD[N_NODES];   // atomic cursors, local-based
__device__ int g_curB[N_NODES];
__device__ int g_adjD[NNZ];       // grouped by src: stores dst ids
__device__ int g_adjB[NNZ];       // grouped by dst: stores src ids
__device__ int g_bsumD[NB1];      // scanned block offsets (global base per block)
__device__ int g_bsumB[NB1];

// ---------------- CSR build ----------------
__global__ void k_zero_counts() {
    int i = blockIdx.x * blockDim.x + threadIdx.x;
    if (i < N_NODES) { g_degD[i] = 0; g_degB[i] = 0; }
}

// 2 edges per thread via int2 loads on each half
__global__ void k_count(const int* __restrict__ ei) {
    int i = blockIdx.x * blockDim.x + threadIdx.x;
    if (i < NNZ / 2) {
        int2 s2 = ((const int2*)ei)[i];
        int2 d2 = ((const int2*)(ei + NNZ))[i];
        atomicAdd(&g_degD[s2.x], 1);
        atomicAdd(&g_degD[s2.y], 1);
        atomicAdd(&g_degB[d2.x], 1);
        atomicAdd(&g_degB[d2.y], 1);
    }
}

// per-block exclusive scan of 1024 elems; writes LOCAL exclusive prefix to
// BOTH off and cur; block totals -> bsums. Consumers add bsums[i>>10].
__global__ void k_scan1() {
    int which = blockIdx.y;
    const int* __restrict__ in  = which ? g_degB  : g_degD;
    int* __restrict__ out       = which ? g_offB  : g_offD;
    int* __restrict__ cur       = which ? g_curB  : g_curD;
    int* __restrict__ bsums     = which ? g_bsumB : g_bsumD;
    __shared__ int sh[1024];
    int g = blockIdx.x * 1024 + threadIdx.x;
    int v = (g < N_NODES) ? in[g] : 0;
    sh[threadIdx.x] = v;
    __syncthreads();
    #pragma unroll
    for (int off = 1; off < 1024; off <<= 1) {
        int t = (threadIdx.x >= off) ? sh[threadIdx.x - off] : 0;
        __syncthreads();
        sh[threadIdx.x] += t;
        __syncthreads();
    }
    if (g < N_NODES) {
        int e = sh[threadIdx.x] - v;   // local exclusive
        out[g] = e;
        cur[g] = e;
    }
    if (threadIdx.x == 1023) bsums[blockIdx.x] = sh[1023];
}

// single-block exclusive scan of NB1 block sums
__global__ void k_scan2() {
    int* __restrict__ bsums = blockIdx.y ? g_bsumB : g_bsumD;
    __shared__ int sh[128];
    int v = (threadIdx.x < NB1) ? bsums[threadIdx.x] : 0;
    sh[threadIdx.x] = v;
    __syncthreads();
    #pragma unroll
    for (int off = 1; off < 128; off <<= 1) {
        int t = (threadIdx.x >= off) ? sh[threadIdx.x - off] : 0;
        __syncthreads();
        sh[threadIdx.x] += t;
        __syncthreads();
    }
    if (threadIdx.x < NB1) bsums[threadIdx.x] = sh[threadIdx.x] - v;
}

// fill dst-grouped CSR (needed by gather_n2e) — critical path.
// cursor is block-local; add scanned block base for the global slot.
__global__ void k_fillB(const int* __restrict__ ei) {
    int i = blockIdx.x * blockDim.x + threadIdx.x;
    if (i < NNZ / 2) {
        int2 s2 = ((const int2*)ei)[i];
        int2 d2 = ((const int2*)(ei + NNZ))[i];
        int p0 = atomicAdd(&g_curB[d2.x], 1) + __ldg(&g_bsumB[d2.x >> 10]);
        g_adjB[p0] = s2.x;
        int p1 = atomicAdd(&g_curB[d2.y], 1) + __ldg(&g_bsumB[d2.y >> 10]);
        g_adjB[p1] = s2.y;
    }
}

// fill src-grouped CSR (needed by gather_e2n) — overlapped off-path
__global__ void k_fillD(const int* __restrict__ ei) {
    int i = blockIdx.x * blockDim.x + threadIdx.x;
    if (i < NNZ / 2) {
        int2 s2 = ((const int2*)ei)[i];
        int2 d2 = ((const int2*)(ei + NNZ))[i];
        int p0 = atomicAdd(&g_curD[s2.x], 1) + __ldg(&g_bsumD[s2.x >> 10]);
        g_adjD[p0] = d2.x;
        int p1 = atomicAdd(&g_curD[s2.y], 1) + __ldg(&g_bsumD[s2.y >> 10]);
        g_adjD[p1] = d2.y;
    }
}

// ---------------- W prep: transpose + f16, both weights in one launch ----
// blockIdx.y: 0 -> W1, 1 -> W2
__global__ void k_prep_w(const float* __restrict__ W1,
                         const float* __restrict__ W2) {
    int which = blockIdx.y;
    const float* __restrict__ W = which ? W2 : W1;
    __half* dh = which ? g_W2h : g_W1h;
    int i = blockIdx.x * blockDim.x + threadIdx.x;   // 65536 per slice
    int k = i >> 8;
    int n = i & 255;
    dh[n * F_DIM + k] = __float2half_rn(W[k * F_DIM + n]);  // coalesced in n
}

// ---------------- HMMA GEMM via mma.sync (portable) ----------------
// g_xt[M,256](fp16) = A[M,256] @ W[256,256], single-pass f16, fp32 accum.
// CTA: 256 threads (8 warps as 4m x 2n), tile 128x128, K chunk 32.
#define KCH 32
#define LDA 40                        // padded row stride (halves)

__device__ __forceinline__ uint32_t smem_u32(const void* p) {
    uint32_t a;
    asm("{ .reg .u64 t; cvta.to.shared.u64 t, %1; cvt.u32.u64 %0, t; }"
        : "=r"(a) : "l"(p));
    return a;
}
__device__ __forceinline__ void ldsm4(uint32_t& r0, uint32_t& r1,
                                      uint32_t& r2, uint32_t& r3, uint32_t a) {
    asm volatile("ldmatrix.sync.aligned.m8n8.x4.shared.b16 {%0,%1,%2,%3}, [%4];"
                 : "=r"(r0), "=r"(r1), "=r"(r2), "=r"(r3) : "r"(a));
}
__device__ __forceinline__ void mma16816(float* d, const uint32_t* a,
                                         const uint32_t* b) {
    asm volatile(
        "mma.sync.aligned.m16n8k16.row.col.f32.f16.f16.f32 "
        "{%0,%1,%2,%3},{%4,%5,%6,%7},{%8,%9},{%0,%1,%2,%3};"
        : "+f"(d[0]), "+f"(d[1]), "+f"(d[2]), "+f"(d[3])
        : "r"(a[0]), "r"(a[1]), "r"(a[2]), "r"(a[3]), "r"(b[0]), "r"(b[1]));
}

__global__ __launch_bounds__(256, 2)
void k_gemm_mma(const float* __restrict__ A_ext, int use_h, int use_w2) {
    __shared__ __half As[128 * LDA];
    __shared__ __half Bs[128 * LDA];

    const __half* __restrict__ Wh = use_w2 ? g_W2h : g_W1h;

    int tid  = threadIdx.x;
    int wid  = tid >> 5;
    int lane = tid & 31;
    int wm   = wid & 3;        // warp m index (4) -> rows wm*32
    int wn   = wid >> 2;       // warp n index (2) -> cols wn*64
    int bm   = blockIdx.y * 128;
    int bn   = blockIdx.x * 128;

    uint32_t sA = smem_u32(As);
    uint32_t sB = smem_u32(Bs);

    float acc[2][8][4];
    #pragma unroll
    for (int i = 0; i < 2; ++i)
        #pragma unroll
        for (int j = 0; j < 8; ++j)
            #pragma unroll
            for (int c = 0; c < 4; ++c) acc[i][j][c] = 0.f;

    int lanerow = lane & 15;
    int lanek   = (lane >> 4) << 3;   // 0 or 8

    for (int k0 = 0; k0 < F_DIM; k0 += KCH) {
        // ---- A tile: 128 rows x 32 halves ----
        if (use_h) {
            #pragma unroll
            for (int l = 0; l < 2; ++l) {
                int idx = tid + l * 256;   // 0..511
                int m = idx >> 2;          // 0..127
                int j = idx & 3;           // uint4 -> klocal j*8
                int grow = bm + m;
                uint4 v = make_uint4(0u, 0u, 0u, 0u);
                if (grow < N_NODES)
                    v = *(const uint4*)(g_h + (size_t)grow * F_DIM + k0 + j * 8);
                *(uint4*)&As[m * LDA + j * 8] = v;
            }
        } else {
            #pragma unroll
            for (int l = 0; l < 4; ++l) {
                int idx = tid + l * 256;   // 0..1023
                int m = idx >> 3;          // 0..127
                int j = idx & 7;           // float4 -> klocal j*4
                int grow = bm + m;
                float4 v = make_float4(0.f, 0.f, 0.f, 0.f);
                if (grow < N_NODES)
                    v = *(const float4*)(A_ext + (size_t)grow * F_DIM + k0 + j * 4);
                int o = m * LDA + j * 4;
                *(__half2*)&As[o]     = __floats2half2_rn(v.x, v.y);
                *(__half2*)&As[o + 2] = __floats2half2_rn(v.z, v.w);
            }
        }
        // ---- B tile: 128 n-rows x 32 halves from Wh [n][k] ----
        {
            #pragma unroll
            for (int l = 0; l < 2; ++l) {
                int id2 = tid + l * 256;
                int n = id2 >> 2;          // 0..127
                int j = id2 & 3;           // uint4 -> klocal j*8
                *(uint4*)&Bs[n * LDA + j * 8] =
                    *(const uint4*)(Wh + (size_t)(bn + n) * F_DIM + k0 + j * 8);
            }
        }
        __syncthreads();

        #pragma unroll
        for (int ks = 0; ks < KCH; ks += 16) {
            uint32_t a[2][4];
            #pragma unroll
            for (int mf = 0; mf < 2; ++mf) {
                uint32_t off = (uint32_t)((wm * 32 + mf * 16 + lanerow) * LDA
                                          + ks + lanek) * 2;
                ldsm4(a[mf][0], a[mf][1], a[mf][2], a[mf][3], sA + off);
            }
            #pragma unroll
            for (int h = 0; h < 2; ++h) {      // two halves of 4 n-tiles
                uint32_t b[4][2];
                #pragma unroll
                for (int g = 0; g < 2; ++g) {  // each x4 covers 2 n-tiles
                    uint32_t off = (uint32_t)((wn * 64 + (h * 2 + g) * 16
                                               + lanerow) * LDA + ks + lanek) * 2;
                    uint32_t r0, r1, r2, r3;
                    ldsm4(r0, r1, r2, r3, sB + off);
                    b[g * 2][0] = r0; b[g * 2][1] = r2;
                    b[g * 2 + 1][0] = r1; b[g * 2 + 1][1] = r3;
                }
                #pragma unroll
                for (int mf = 0; mf < 2; ++mf)
                    #pragma unroll
                    for (int t = 0; t < 4; ++t)
                        mma16816(acc[mf][h * 4 + t], a[mf], b[t]);
            }
        }
        __syncthreads();
    }

    // ---- epilogue: write fp16 g_xt ----
    int qrow = lane >> 2;          // 0..7
    int qcol = (lane & 3) * 2;     // 0,2,4,6
    #pragma unroll
    for (int mf = 0; mf < 2; ++mf) {
        int r0 = bm + wm * 32 + mf * 16 + qrow;
        #pragma unroll
        for (int nt = 0; nt < 8; ++nt) {
            int col = bn + wn * 64 + nt * 8 + qcol;
            float* d = acc[mf][nt];
            if (r0 < N_NODES)
                *(__half2*)(g_xt + (size_t)r0 * F_DIM + col) =
                    __floats2half2_rn(d[0], d[1]);
            if (r0 + 8 < N_NODES)
                *(__half2*)(g_xt + (size_t)(r0 + 8) * F_DIM + col) =
                    __floats2half2_rn(d[2], d[3]);
        }
    }
}

// ---------------- fp16 row helpers ----------------
__device__ __forceinline__ void acc8_from_u4(float* acc, uint4 v) {
    __half2* h = (__half2*)&v;
    #pragma unroll
    for (int i = 0; i < 4; ++i) {
        float2 f = __half22float2(h[i]);
        acc[2 * i]     += f.x;
        acc[2 * i + 1] += f.y;
    }
}
__device__ __forceinline__ uint4 u4_from_8f(const float* s) {
    uint4 v;
    __half2* h = (__half2*)&v;
    #pragma unroll
    for (int i = 0; i < 4; ++i)
        h[i] = __floats2half2_rn(s[2 * i], s[2 * i + 1]);
    return v;
}

// ------- gather node -> hyperedge: g_m[e] = Binv[e] * sum_{src in e} g_xt[src]
__global__ __launch_bounds__(256)
void k_gather_n2e() {
    int w = (blockIdx.x * blockDim.x + threadIdx.x) >> 5;
    if (w >= N_NODES) return;
    int lane = threadIdx.x & 31;
    int off = g_offB[w] + __ldg(&g_bsumB[w >> 10]);   // local + block base
    int deg = g_degB[w];
    const int* __restrict__ adj = g_adjB + off;

    float acc[8] = {0.f, 0.f, 0.f, 0.f, 0.f, 0.f, 0.f, 0.f};
    #pragma unroll 4
    for (int j = 0; j < deg; ++j) {
        int s = __ldg(adj + j);
        uint4 v = __ldg((const uint4*)(g_xt + (size_t)s * F_DIM) + lane);
        acc8_from_u4(acc, v);
    }
    float binv = deg > 0 ? 1.f / (float)deg : 0.f;
    #pragma unroll
    for (int i = 0; i < 8; ++i) acc[i] *= binv;
    *((uint4*)(g_m + (size_t)w * F_DIM) + lane) = u4_from_8f(acc);
}

__device__ __forceinline__ float prelu(float v, float a) {
    return v >= 0.f ? v : a * v;
}

// ------- gather hyperedge -> node, fused epilogue
// use_out: 1 -> write fp32 dout (+x residual), 0 -> write fp16 g_h
__global__ __launch_bounds__(256)
void k_gather_e2n(float* __restrict__ dout, const float* __restrict__ bias,
                  const float* __restrict__ aP, const float* __restrict__ xres,
                  int use_out, int addres) {
    int w = (blockIdx.x * blockDim.x + threadIdx.x) >> 5;
    if (w >= N_NODES) return;
    int lane = threadIdx.x & 31;
    int off = g_offD[w] + __ldg(&g_bsumD[w >> 10]);   // local + block base
    int deg = g_degD[w];
    const int* __restrict__ adj = g_adjD + off;

    float acc[8] = {0.f, 0.f, 0.f, 0.f, 0.f, 0.f, 0.f, 0.f};
    #pragma unroll 4
    for (int j = 0; j < deg; ++j) {
        int e = __ldg(adj + j);
        uint4 v = __ldg((const uint4*)(g_m + (size_t)e * F_DIM) + lane);
        acc8_from_u4(acc, v);
    }
    float dinv = deg > 0 ? 1.f / (float)deg : 0.f;
    float av = __ldg(aP);
    float4 bb0 = *(const float4*)(bias + lane * 8);
    float4 bb1 = *(const float4*)(bias + lane * 8 + 4);
    float r[8];
    r[0] = fmaf(acc[0], dinv, bb0.x); r[1] = fmaf(acc[1], dinv, bb0.y);
    r[2] = fmaf(acc[2], dinv, bb0.z); r[3] = fmaf(acc[3], dinv, bb0.w);
    r[4] = fmaf(acc[4], dinv, bb1.x); r[5] = fmaf(acc[5], dinv, bb1.y);
    r[6] = fmaf(acc[6], dinv, bb1.z); r[7] = fmaf(acc[7], dinv, bb1.w);

    if (addres) {
        const float* xr = xres + (size_t)w * F_DIM + lane * 8;
        float4 x0 = __ldg((const float4*)xr);
        float4 x1 = __ldg((const float4*)(xr + 4));
        r[0] += x0.x; r[1] += x0.y; r[2] += x0.z; r[3] += x0.w;
        r[4] += x1.x; r[5] += x1.y; r[6] += x1.z; r[7] += x1.w;
    }
    #pragma unroll
    for (int i = 0; i < 8; ++i) r[i] = prelu(r[i], av);

    if (use_out) {
        float* dr = dout + (size_t)w * F_DIM + lane * 8;
        *(float4*)dr       = make_float4(r[0], r[1], r[2], r[3]);
        *(float4*)(dr + 4) = make_float4(r[4], r[5], r[6], r[7]);
    } else {
        *((uint4*)(g_h + (size_t)w * F_DIM) + lane) = u4_from_8f(r);
    }
}

// ---------------- launch ----------------
extern "C" void kernel_launch(void* const* d_in, const int* in_sizes, int n_in,
                              void* d_out, int out_size) {
    const float* x  = (const float*)d_in[0];
    const int*   ei = (const int*)  d_in[1];
    const float* W1 = (const float*)d_in[2];
    const float* b1 = (const float*)d_in[3];
    const float* W2 = (const float*)d_in[4];
    const float* b2 = (const float*)d_in[5];
    const float* a  = (const float*)d_in[6];
    float* out = (float*)d_out;

    // Host-side objects created once (no device memory involved). The launched
    // work is identical on every call.
    static cudaStream_t s_side = [] {
        cudaStream_t s = nullptr;
        cudaStreamCreateWithFlags(&s, cudaStreamNonBlocking);
        return s;
    }();
    static cudaStream_t s_fill = [] {
        cudaStream_t s = nullptr;
        cudaStreamCreateWithFlags(&s, cudaStreamNonBlocking);
        return s;
    }();
    static cudaEvent_t e_fork = [] {
        cudaEvent_t e = nullptr;
        cudaEventCreateWithFlags(&e, cudaEventDisableTiming);
        return e;
    }();
    static cudaEvent_t e_gemm1 = [] {
        cudaEvent_t e = nullptr;
        cudaEventCreateWithFlags(&e, cudaEventDisableTiming);
        return e;
    }();
    static cudaEvent_t e_scan = [] {
        cudaEvent_t e = nullptr;
        cudaEventCreateWithFlags(&e, cudaEventDisableTiming);
        return e;
    }();
    static cudaEvent_t e_fillD = [] {
        cudaEvent_t e = nullptr;
        cudaEventCreateWithFlags(&e, cudaEventDisableTiming);
        return e;
    }();

    const int GAT = (N_NODES * 32 + 255) / 256;   // warp per node
    dim3 ggrid(2, (N_NODES + 127) / 128);         // 2 n-tiles x 782 m-tiles

    // ---- fork: W prep + GEMM-1 on side stream ----
    cudaEventRecord(e_fork, 0);
    cudaStreamWaitEvent(s_side, e_fork, 0);
    k_prep_w<<<dim3(F_DIM * F_DIM / 256, 2), 256, 0, s_side>>>(W1, W2);
    k_gemm_mma<<<ggrid, 256, 0, s_side>>>(x, 0, 0);
    cudaEventRecord(e_gemm1, s_side);

    // ---- main stream: CSR build, B-side only on the critical path ----
    k_zero_counts<<<(N_NODES + 255) / 256, 256>>>();
    k_count<<<(NNZ / 2 + 255) / 256, 256>>>(ei);
    k_scan1<<<dim3(NB1, 2), 1024>>>();   // writes local excl to off AND cur
    k_scan2<<<dim3(1, 2), 128>>>();      // block bases; consumers add inline
    cudaEventRecord(e_scan, 0);
    k_fillB<<<(NNZ / 2 + 255) / 256, 256>>>(ei);

    // ---- fill D-CSR off the critical path (overlaps gather_n2e) ----
    cudaStreamWaitEvent(s_fill, e_scan, 0);
    k_fillD<<<(NNZ / 2 + 255) / 256, 256, 0, s_fill>>>(ei);
    cudaEventRecord(e_fillD, s_fill);

    // join with GEMM-1, then layer-1 gathers
    cudaStreamWaitEvent(0, e_gemm1, 0);
    k_gather_n2e<<<GAT, 256>>>();
    cudaStreamWaitEvent(0, e_fillD, 0);
    k_gather_e2n<<<GAT, 256>>>(out, b1, a, x, 0, 0);

    // ---- layer 2 ----
    k_gemm_mma<<<ggrid, 256>>>(x /*unused*/, 1, 1);
    k_gather_n2e<<<GAT, 256>>>();
    k_gather_e2n<<<GAT, 256>>>(out, b2, a, x, 1, 1);
}

// round 16
// speedup vs baseline: 1.0386x; 1.0102x over previous
#include <cuda_runtime.h>
#include <cuda_fp16.h>
#include <cstddef>
#include <cstdint>

#define N_NODES 100000
#define F_DIM   256
#define NNZ     1600000
#define NB1     98          // ceil(N_NODES/1024)

// ---------------- scratch (no allocation allowed) ----------------
// __device__ symbols are ONLY referenced from device code, never passed
// as kernel arguments from host.
__device__ __half g_xt[(size_t)N_NODES * F_DIM];  // GEMM output, fp16 (gathered)
__device__ __half g_m [(size_t)N_NODES * F_DIM];  // hyperedge accum, fp16 (gathered)
__device__ __half g_h [(size_t)N_NODES * F_DIM];  // layer-1 hidden, fp16

__device__ __half g_W1h[F_DIM * F_DIM];  // W1^T f16  [n][k]
__device__ __half g_W2h[F_DIM * F_DIM];  // W2^T f16  [n][k]

__device__ int g_degD[N_NODES];
__device__ int g_degB[N_NODES];
__device__ int g_offD[N_NODES];   // BLOCK-LOCAL exclusive prefix
__device__ int g_offB[N_NODES];   // BLOCK-LOCAL exclusive prefix
__device__ int g_curD[N_NODES];   // atomic cursors, local-based
__device__ int g_curB[N_NODES];
__device__ int g_adjD[NNZ];       // grouped by src: stores dst ids
__device__ int g_adjB[NNZ];       // grouped by dst: stores src ids
__device__ int g_bsumD[NB1];      // scanned block offsets (global base per block)
__device__ int g_bsumB[NB1];

// ---------------- CSR build ----------------
__global__ void k_zero_counts() {
    int i = blockIdx.x * blockDim.x + threadIdx.x;
    if (i < N_NODES) { g_degD[i] = 0; g_degB[i] = 0; }
}

// 2 edges per thread via int2 loads on each half
__global__ void k_count(const int* __restrict__ ei) {
    int i = blockIdx.x * blockDim.x + threadIdx.x;
    if (i < NNZ / 2) {
        int2 s2 = ((const int2*)ei)[i];
        int2 d2 = ((const int2*)(ei + NNZ))[i];
        atomicAdd(&g_degD[s2.x], 1);
        atomicAdd(&g_degD[s2.y], 1);
        atomicAdd(&g_degB[d2.x], 1);
        atomicAdd(&g_degB[d2.y], 1);
    }
}

// per-block exclusive scan of 1024 elems; writes LOCAL exclusive prefix to
// BOTH off and cur; block totals -> bsums. Consumers add bsums[i>>10].
__global__ void k_scan1() {
    int which = blockIdx.y;
    const int* __restrict__ in  = which ? g_degB  : g_degD;
    int* __restrict__ out       = which ? g_offB  : g_offD;
    int* __restrict__ cur       = which ? g_curB  : g_curD;
    int* __restrict__ bsums     = which ? g_bsumB : g_bsumD;
    __shared__ int sh[1024];
    int g = blockIdx.x * 1024 + threadIdx.x;
    int v = (g < N_NODES) ? in[g] : 0;
    sh[threadIdx.x] = v;
    __syncthreads();
    #pragma unroll
    for (int off = 1; off < 1024; off <<= 1) {
        int t = (threadIdx.x >= off) ? sh[threadIdx.x - off] : 0;
        __syncthreads();
        sh[threadIdx.x] += t;
        __syncthreads();
    }
    if (g < N_NODES) {
        int e = sh[threadIdx.x] - v;   // local exclusive
        out[g] = e;
        cur[g] = e;
    }
    if (threadIdx.x == 1023) bsums[blockIdx.x] = sh[1023];
}

// single-block exclusive scan of NB1 block sums
__global__ void k_scan2() {
    int* __restrict__ bsums = blockIdx.y ? g_bsumB : g_bsumD;
    __shared__ int sh[128];
    int v = (threadIdx.x < NB1) ? bsums[threadIdx.x] : 0;
    sh[threadIdx.x] = v;
    __syncthreads();
    #pragma unroll
    for (int off = 1; off < 128; off <<= 1) {
        int t = (threadIdx.x >= off) ? sh[threadIdx.x - off] : 0;
        __syncthreads();
        sh[threadIdx.x] += t;
        __syncthreads();
    }
    if (threadIdx.x < NB1) bsums[threadIdx.x] = sh[threadIdx.x] - v;
}

// fill dst-grouped CSR (needed by gather_n2e) — critical path.
// cursor is block-local; add scanned block base for the global slot.
__global__ void k_fillB(const int* __restrict__ ei) {
    int i = blockIdx.x * blockDim.x + threadIdx.x;
    if (i < NNZ / 2) {
        int2 s2 = ((const int2*)ei)[i];
        int2 d2 = ((const int2*)(ei + NNZ))[i];
        int p0 = atomicAdd(&g_curB[d2.x], 1) + __ldg(&g_bsumB[d2.x >> 10]);
        g_adjB[p0] = s2.x;
        int p1 = atomicAdd(&g_curB[d2.y], 1) + __ldg(&g_bsumB[d2.y >> 10]);
        g_adjB[p1] = s2.y;
    }
}

// fill src-grouped CSR (needed by gather_e2n) — overlapped off-path
__global__ void k_fillD(const int* __restrict__ ei) {
    int i = blockIdx.x * blockDim.x + threadIdx.x;
    if (i < NNZ / 2) {
        int2 s2 = ((const int2*)ei)[i];
        int2 d2 = ((const int2*)(ei + NNZ))[i];
        int p0 = atomicAdd(&g_curD[s2.x], 1) + __ldg(&g_bsumD[s2.x >> 10]);
        g_adjD[p0] = d2.x;
        int p1 = atomicAdd(&g_curD[s2.y], 1) + __ldg(&g_bsumD[s2.y >> 10]);
        g_adjD[p1] = d2.y;
    }
}

// ---------------- W prep: transpose + f16, both weights in one launch ----
// blockIdx.y: 0 -> W1, 1 -> W2
__global__ void k_prep_w(const float* __restrict__ W1,
                         const float* __restrict__ W2) {
    int which = blockIdx.y;
    const float* __restrict__ W = which ? W2 : W1;
    __half* dh = which ? g_W2h : g_W1h;
    int i = blockIdx.x * blockDim.x + threadIdx.x;   // 65536 per slice
    int k = i >> 8;
    int n = i & 255;
    dh[n * F_DIM + k] = __float2half_rn(W[k * F_DIM + n]);  // coalesced in n
}

// ---------------- HMMA GEMM via mma.sync (portable) ----------------
// g_xt[M,256](fp16) = A[M,256] @ W[256,256], single-pass f16, fp32 accum.
// CTA: 256 threads (8 warps as 4m x 2n), tile 128x128, K chunk 32.
#define KCH 32
#define LDA 40                        // padded row stride (halves)

__device__ __forceinline__ uint32_t smem_u32(const void* p) {
    uint32_t a;
    asm("{ .reg .u64 t; cvta.to.shared.u64 t, %1; cvt.u32.u64 %0, t; }"
        : "=r"(a) : "l"(p));
    return a;
}
__device__ __forceinline__ void ldsm4(uint32_t& r0, uint32_t& r1,
                                      uint32_t& r2, uint32_t& r3, uint32_t a) {
    asm volatile("ldmatrix.sync.aligned.m8n8.x4.shared.b16 {%0,%1,%2,%3}, [%4];"
                 : "=r"(r0), "=r"(r1), "=r"(r2), "=r"(r3) : "r"(a));
}
__device__ __forceinline__ void mma16816(float* d, const uint32_t* a,
                                         const uint32_t* b) {
    asm volatile(
        "mma.sync.aligned.m16n8k16.row.col.f32.f16.f16.f32 "
        "{%0,%1,%2,%3},{%4,%5,%6,%7},{%8,%9},{%0,%1,%2,%3};"
        : "+f"(d[0]), "+f"(d[1]), "+f"(d[2]), "+f"(d[3])
        : "r"(a[0]), "r"(a[1]), "r"(a[2]), "r"(a[3]), "r"(b[0]), "r"(b[1]));
}

__global__ __launch_bounds__(256, 2)
void k_gemm_mma(const float* __restrict__ A_ext, int use_h, int use_w2) {
    __shared__ __half As[128 * LDA];
    __shared__ __half Bs[128 * LDA];

    const __half* __restrict__ Wh = use_w2 ? g_W2h : g_W1h;

    int tid  = threadIdx.x;
    int wid  = tid >> 5;
    int lane = tid & 31;
    int wm   = wid & 3;        // warp m index (4) -> rows wm*32
    int wn   = wid >> 2;       // warp n index (2) -> cols wn*64
    int bm   = blockIdx.y * 128;
    int bn   = blockIdx.x * 128;

    uint32_t sA = smem_u32(As);
    uint32_t sB = smem_u32(Bs);

    float acc[2][8][4];
    #pragma unroll
    for (int i = 0; i < 2; ++i)
        #pragma unroll
        for (int j = 0; j < 8; ++j)
            #pragma unroll
            for (int c = 0; c < 4; ++c) acc[i][j][c] = 0.f;

    int lanerow = lane & 15;
    int lanek   = (lane >> 4) << 3;   // 0 or 8

    for (int k0 = 0; k0 < F_DIM; k0 += KCH) {
        // ---- A tile: 128 rows x 32 halves ----
        if (use_h) {
            #pragma unroll
            for (int l = 0; l < 2; ++l) {
                int idx = tid + l * 256;   // 0..511
                int m = idx >> 2;          // 0..127
                int j = idx & 3;           // uint4 -> klocal j*8
                int grow = bm + m;
                uint4 v = make_uint4(0u, 0u, 0u, 0u);
                if (grow < N_NODES)
                    v = *(const uint4*)(g_h + (size_t)grow * F_DIM + k0 + j * 8);
                *(uint4*)&As[m * LDA + j * 8] = v;
            }
        } else {
            #pragma unroll
            for (int l = 0; l < 4; ++l) {
                int idx = tid + l * 256;   // 0..1023
                int m = idx >> 3;          // 0..127
                int j = idx & 7;           // float4 -> klocal j*4
                int grow = bm + m;
                float4 v = make_float4(0.f, 0.f, 0.f, 0.f);
                if (grow < N_NODES)
                    v = *(const float4*)(A_ext + (size_t)grow * F_DIM + k0 + j * 4);
                int o = m * LDA + j * 4;
                *(__half2*)&As[o]     = __floats2half2_rn(v.x, v.y);
                *(__half2*)&As[o + 2] = __floats2half2_rn(v.z, v.w);
            }
        }
        // ---- B tile: 128 n-rows x 32 halves from Wh [n][k] ----
        {
            #pragma unroll
            for (int l = 0; l < 2; ++l) {
                int id2 = tid + l * 256;
                int n = id2 >> 2;          // 0..127
                int j = id2 & 3;           // uint4 -> klocal j*8
                *(uint4*)&Bs[n * LDA + j * 8] =
                    *(const uint4*)(Wh + (size_t)(bn + n) * F_DIM + k0 + j * 8);
            }
        }
        __syncthreads();

        #pragma unroll
        for (int ks = 0; ks < KCH; ks += 16) {
            uint32_t a[2][4];
            #pragma unroll
            for (int mf = 0; mf < 2; ++mf) {
                uint32_t off = (uint32_t)((wm * 32 + mf * 16 + lanerow) * LDA
                                          + ks + lanek) * 2;
                ldsm4(a[mf][0], a[mf][1], a[mf][2], a[mf][3], sA + off);
            }
            #pragma unroll
            for (int h = 0; h < 2; ++h) {      // two halves of 4 n-tiles
                uint32_t b[4][2];
                #pragma unroll
                for (int g = 0; g < 2; ++g) {  // each x4 covers 2 n-tiles
                    uint32_t off = (uint32_t)((wn * 64 + (h * 2 + g) * 16
                                               + lanerow) * LDA + ks + lanek) * 2;
                    uint32_t r0, r1, r2, r3;
                    ldsm4(r0, r1, r2, r3, sB + off);
                    b[g * 2][0] = r0; b[g * 2][1] = r2;
                    b[g * 2 + 1][0] = r1; b[g * 2 + 1][1] = r3;
                }
                #pragma unroll
                for (int mf = 0; mf < 2; ++mf)
                    #pragma unroll
                    for (int t = 0; t < 4; ++t)
                        mma16816(acc[mf][h * 4 + t], a[mf], b[t]);
            }
        }
        __syncthreads();
    }

    // ---- epilogue: write fp16 g_xt ----
    int qrow = lane >> 2;          // 0..7
    int qcol = (lane & 3) * 2;     // 0,2,4,6
    #pragma unroll
    for (int mf = 0; mf < 2; ++mf) {
        int r0 = bm + wm * 32 + mf * 16 + qrow;
        #pragma unroll
        for (int nt = 0; nt < 8; ++nt) {
            int col = bn + wn * 64 + nt * 8 + qcol;
            float* d = acc[mf][nt];
            if (r0 < N_NODES)
                *(__half2*)(g_xt + (size_t)r0 * F_DIM + col) =
                    __floats2half2_rn(d[0], d[1]);
            if (r0 + 8 < N_NODES)
                *(__half2*)(g_xt + (size_t)(r0 + 8) * F_DIM + col) =
                    __floats2half2_rn(d[2], d[3]);
        }
    }
}

// ---------------- fp16 row helpers ----------------
__device__ __forceinline__ void acc8_from_u4(float* acc, uint4 v) {
    __half2* h = (__half2*)&v;
    #pragma unroll
    for (int i = 0; i < 4; ++i) {
        float2 f = __half22float2(h[i]);
        acc[2 * i]     += f.x;
        acc[2 * i + 1] += f.y;
    }
}
__device__ __forceinline__ uint4 u4_from_8f(const float* s) {
    uint4 v;
    __half2* h = (__half2*)&v;
    #pragma unroll
    for (int i = 0; i < 4; ++i)
        h[i] = __floats2half2_rn(s[2 * i], s[2 * i + 1]);
    return v;
}

// ------- gather node -> hyperedge: g_m[e] = Binv[e] * sum_{src in e} g_xt[src]
__global__ __launch_bounds__(256)
void k_gather_n2e() {
    int w = (blockIdx.x * blockDim.x + threadIdx.x) >> 5;
    if (w >= N_NODES) return;
    int lane = threadIdx.x & 31;
    int off = g_offB[w] + __ldg(&g_bsumB[w >> 10]);   // local + block base
    int deg = g_degB[w];
    const int* __restrict__ adj = g_adjB + off;

    float acc[8] = {0.f, 0.f, 0.f, 0.f, 0.f, 0.f, 0.f, 0.f};
    #pragma unroll 8
    for (int j = 0; j < deg; ++j) {
        int s = __ldg(adj + j);
        uint4 v = __ldg((const uint4*)(g_xt + (size_t)s * F_DIM) + lane);
        acc8_from_u4(acc, v);
    }
    float binv = deg > 0 ? 1.f / (float)deg : 0.f;
    #pragma unroll
    for (int i = 0; i < 8; ++i) acc[i] *= binv;
    *((uint4*)(g_m + (size_t)w * F_DIM) + lane) = u4_from_8f(acc);
}

__device__ __forceinline__ float prelu(float v, float a) {
    return v >= 0.f ? v : a * v;
}

// ------- gather hyperedge -> node, fused epilogue
// use_out: 1 -> write fp32 dout (+x residual), 0 -> write fp16 g_h
__global__ __launch_bounds__(256)
void k_gather_e2n(float* __restrict__ dout, const float* __restrict__ bias,
                  const float* __restrict__ aP, const float* __restrict__ xres,
                  int use_out, int addres) {
    int w = (blockIdx.x * blockDim.x + threadIdx.x) >> 5;
    if (w >= N_NODES) return;
    int lane = threadIdx.x & 31;
    int off = g_offD[w] + __ldg(&g_bsumD[w >> 10]);   // local + block base
    int deg = g_degD[w];
    const int* __restrict__ adj = g_adjD + off;

    float acc[8] = {0.f, 0.f, 0.f, 0.f, 0.f, 0.f, 0.f, 0.f};
    #pragma unroll 8
    for (int j = 0; j < deg; ++j) {
        int e = __ldg(adj + j);
        uint4 v = __ldg((const uint4*)(g_m + (size_t)e * F_DIM) + lane);
        acc8_from_u4(acc, v);
    }
    float dinv = deg > 0 ? 1.f / (float)deg : 0.f;
    float av = __ldg(aP);
    float4 bb0 = *(const float4*)(bias + lane * 8);
    float4 bb1 = *(const float4*)(bias + lane * 8 + 4);
    float r[8];
    r[0] = fmaf(acc[0], dinv, bb0.x); r[1] = fmaf(acc[1], dinv, bb0.y);
    r[2] = fmaf(acc[2], dinv, bb0.z); r[3] = fmaf(acc[3], dinv, bb0.w);
    r[4] = fmaf(acc[4], dinv, bb1.x); r[5] = fmaf(acc[5], dinv, bb1.y);
    r[6] = fmaf(acc[6], dinv, bb1.z); r[7] = fmaf(acc[7], dinv, bb1.w);

    if (addres) {
        const float* xr = xres + (size_t)w * F_DIM + lane * 8;
        float4 x0 = __ldg((const float4*)xr);
        float4 x1 = __ldg((const float4*)(xr + 4));
        r[0] += x0.x; r[1] += x0.y; r[2] += x0.z; r[3] += x0.w;
        r[4] += x1.x; r[5] += x1.y; r[6] += x1.z; r[7] += x1.w;
    }
    #pragma unroll
    for (int i = 0; i < 8; ++i) r[i] = prelu(r[i], av);

    if (use_out) {
        float* dr = dout + (size_t)w * F_DIM + lane * 8;
        *(float4*)dr       = make_float4(r[0], r[1], r[2], r[3]);
        *(float4*)(dr + 4) = make_float4(r[4], r[5], r[6], r[7]);
    } else {
        *((uint4*)(g_h + (size_t)w * F_DIM) + lane) = u4_from_8f(r);
    }
}

// ---------------- launch ----------------
extern "C" void kernel_launch(void* const* d_in, const int* in_sizes, int n_in,
                              void* d_out, int out_size) {
    const float* x  = (const float*)d_in[0];
    const int*   ei = (const int*)  d_in[1];
    const float* W1 = (const float*)d_in[2];
    const float* b1 = (const float*)d_in[3];
    const float* W2 = (const float*)d_in[4];
    const float* b2 = (const float*)d_in[5];
    const float* a  = (const float*)d_in[6];
    float* out = (float*)d_out;

    // Host-side objects created once (no device memory involved). The launched
    // work is identical on every call.
    static cudaStream_t s_side = [] {
        cudaStream_t s = nullptr;
        cudaStreamCreateWithFlags(&s, cudaStreamNonBlocking);
        return s;
    }();
    static cudaStream_t s_fill = [] {
        cudaStream_t s = nullptr;
        cudaStreamCreateWithFlags(&s, cudaStreamNonBlocking);
        return s;
    }();
    static cudaEvent_t e_fork = [] {
        cudaEvent_t e = nullptr;
        cudaEventCreateWithFlags(&e, cudaEventDisableTiming);
        return e;
    }();
    static cudaEvent_t e_gemm1 = [] {
        cudaEvent_t e = nullptr;
        cudaEventCreateWithFlags(&e, cudaEventDisableTiming);
        return e;
    }();
    static cudaEvent_t e_scan = [] {
        cudaEvent_t e = nullptr;
        cudaEventCreateWithFlags(&e, cudaEventDisableTiming);
        return e;
    }();
    static cudaEvent_t e_fillD = [] {
        cudaEvent_t e = nullptr;
        cudaEventCreateWithFlags(&e, cudaEventDisableTiming);
        return e;
    }();

    const int GAT = (N_NODES * 32 + 255) / 256;   // warp per node
    dim3 ggrid(2, (N_NODES + 127) / 128);         // 2 n-tiles x 782 m-tiles

    // ---- fork: W prep + GEMM-1 on side stream ----
    cudaEventRecord(e_fork, 0);
    cudaStreamWaitEvent(s_side, e_fork, 0);
    k_prep_w<<<dim3(F_DIM * F_DIM / 256, 2), 256, 0, s_side>>>(W1, W2);
    k_gemm_mma<<<ggrid, 256, 0, s_side>>>(x, 0, 0);
    cudaEventRecord(e_gemm1, s_side);

    // ---- main stream: CSR build, B-side only on the critical path ----
    k_zero_counts<<<(N_NODES + 255) / 256, 256>>>();
    k_count<<<(NNZ / 2 + 255) / 256, 256>>>(ei);
    k_scan1<<<dim3(NB1, 2), 1024>>>();   // writes local excl to off AND cur
    k_scan2<<<dim3(1, 2), 128>>>();      // block bases; consumers add inline
    cudaEventRecord(e_scan, 0);
    k_fillB<<<(NNZ / 2 + 255) / 256, 256>>>(ei);

    // ---- fill D-CSR off the critical path (overlaps gather_n2e) ----
    cudaStreamWaitEvent(s_fill, e_scan, 0);
    k_fillD<<<(NNZ / 2 + 255) / 256, 256, 0, s_fill>>>(ei);
    cudaEventRecord(e_fillD, s_fill);

    // join with GEMM-1, then layer-1 gathers
    cudaStreamWaitEvent(0, e_gemm1, 0);
    k_gather_n2e<<<GAT, 256>>>();
    cudaStreamWaitEvent(0, e_fillD, 0);
    k_gather_e2n<<<GAT, 256>>>(out, b1, a, x, 0, 0);

    // ---- layer 2 ----
    k_gemm_mma<<<ggrid, 256>>>(x /*unused*/, 1, 1);
    k_gather_n2e<<<GAT, 256>>>();
    k_gather_e2n<<<GAT, 256>>>(out, b2, a, x, 1, 1);
}